// round 2
// baseline (speedup 1.0000x reference)
#include <cuda_runtime.h>
#include <cstdint>
#include <cstdio>

// Problem constants (fixed by the dataset)
#define HDIM 128
#define NHEAD 8
#define DHEAD 16
#define N_NODES 50000
#define E_EDGES 600000
#define E2_EDGES 600000

// ---------------------------------------------------------------------------
// Scratch (device globals — no allocation allowed)
// ---------------------------------------------------------------------------
__device__ float    g_he0[(size_t)E_EDGES * HDIM];    // 307 MB
__device__ float    g_agg[(size_t)E_EDGES * HDIM];    // 307 MB
__device__ float    g_beta[(size_t)E_EDGES * NHEAD];  // 19 MB (beta, then ex)
__device__ unsigned g_max[(size_t)N_NODES * NHEAD];   // encoded float max
__device__ float    g_den[(size_t)N_NODES * NHEAD];
__device__ float    g_agg2[(size_t)N_NODES * HDIM];   // 25.6 MB
__device__ float    g_wcomb[384 * 128];               // [A1;A2;A3]
__device__ float    g_bcomb[128];                     // b1+b2+b3

// ---------------------------------------------------------------------------
// Monotone float<->uint encoding for atomicMax on floats
// memset(0) == identity: encf(f) > 0 for every finite f.
// ---------------------------------------------------------------------------
__device__ __forceinline__ unsigned encf(float f) {
    int i = __float_as_int(f);
    return (i >= 0) ? ((unsigned)i | 0x80000000u) : ~(unsigned)i;
}
__device__ __forceinline__ float decf(unsigned u) {
    int i = (u & 0x80000000u) ? (int)(u & 0x7FFFFFFFu) : (int)(~u);
    return __int_as_float(i);
}

// ---------------------------------------------------------------------------
// Pre-pack eta weights: g_wcomb = [A1_w; A2_w; A3_w], g_bcomb = b1+b2+b3
// ---------------------------------------------------------------------------
__global__ void prep_kernel(const float* __restrict__ A1w, const float* __restrict__ A2w,
                            const float* __restrict__ A3w, const float* __restrict__ b1,
                            const float* __restrict__ b2, const float* __restrict__ b3) {
    int i = blockIdx.x * blockDim.x + threadIdx.x;
    if (i < 128 * 128) {
        g_wcomb[i]                 = A1w[i];
        g_wcomb[128 * 128 + i]     = A2w[i];
        g_wcomb[2 * 128 * 128 + i] = A3w[i];
    }
    if (i < 128) g_bcomb[i] = b1[i] + b2[i] + b3[i];
}

// ---------------------------------------------------------------------------
// Unified gather-SGEMM.  C[row, 0..127] = epilogue( A(row,:) @ W + bias )
//   MODE 0: A = [x[src], x[tgt], edge_attr[row]]        K=384, epi = relu -> g_he0
//   MODE 1: A = [he0[row], agg[row]]                    K=256, epi = relu -> out_he
//   MODE 2: A = [he0[bsrc], he0[btgt], battr[row]]      K=384, epi = battr + relu -> out_ha
//   MODE 3: A = [x[row], agg2[row]]                     K=256, epi = relu -> out_hx
// BM=64, BN=128, BK=8, 256 threads, thread tile 4x8 (strided by 16)
// ---------------------------------------------------------------------------
template <int MODE, int K>
__global__ void gemm_kernel(const float* __restrict__ p0, const float* __restrict__ p1,
                            const int* __restrict__ idx,
                            const float* __restrict__ W, const float* __restrict__ bias,
                            float* __restrict__ out, int M) {
    __shared__ float As[8][64];
    __shared__ float Bs[8][128];
    __shared__ int   s_i0[64];
    __shared__ int   s_i1[64];

    const int tid = threadIdx.x;
    const int tx = tid & 15;   // N dim (16 lanes x TN=8, stride 16)
    const int ty = tid >> 4;   // M dim (16 lanes x TM=4, stride 16)
    const int m0 = blockIdx.x * 64;

    if (tid < 64) {
        int r = m0 + tid;
        if (r < M) {
            if (MODE == 0 || MODE == 2) {
                s_i0[tid] = idx[r];
                s_i1[tid] = idx[(size_t)M + r];
            }
        }
    }
    __syncthreads();

    float acc[4][8];
#pragma unroll
    for (int i = 0; i < 4; i++)
#pragma unroll
        for (int j = 0; j < 8; j++) acc[i][j] = 0.0f;

    for (int k0 = 0; k0 < K; k0 += 8) {
        if (tid < 128) {
            // A tile: 64 rows x 8 k = 128 float4 loads
            int row = tid >> 1;
            int kk = (tid & 1) * 4;
            int gk = k0 + kk;
            int r = m0 + row;
            float4 v = make_float4(0.f, 0.f, 0.f, 0.f);
            if (r < M) {
                int seg = gk >> 7;
                int col = gk & 127;
                const float* base;
                if (MODE == 0 || MODE == 2) {
                    base = (seg == 0) ? p0 + (size_t)s_i0[row] * HDIM
                         : (seg == 1) ? p0 + (size_t)s_i1[row] * HDIM
                                      : p1 + (size_t)r * HDIM;
                } else {
                    base = (seg == 0) ? p0 + (size_t)r * HDIM
                                      : p1 + (size_t)r * HDIM;
                }
                v = *reinterpret_cast<const float4*>(base + col);
            }
            As[kk + 0][row] = v.x;
            As[kk + 1][row] = v.y;
            As[kk + 2][row] = v.z;
            As[kk + 3][row] = v.w;
        } else {
            // B tile: 8 x 128 = 256 float4, 128 threads x 2
            int u = tid - 128;
            const float4* Bg = reinterpret_cast<const float4*>(W + (size_t)k0 * 128);
            float4* Bss = reinterpret_cast<float4*>(&Bs[0][0]);
            Bss[u]       = Bg[u];
            Bss[u + 128] = Bg[u + 128];
        }
        __syncthreads();

#pragma unroll
        for (int k = 0; k < 8; k++) {
            float a[4], b[8];
#pragma unroll
            for (int i = 0; i < 4; i++) a[i] = As[k][ty + i * 16];
#pragma unroll
            for (int j = 0; j < 8; j++) b[j] = Bs[k][tx + j * 16];
#pragma unroll
            for (int i = 0; i < 4; i++)
#pragma unroll
                for (int j = 0; j < 8; j++) acc[i][j] = fmaf(a[i], b[j], acc[i][j]);
        }
        __syncthreads();
    }

#pragma unroll
    for (int i = 0; i < 4; i++) {
        int row = m0 + ty + i * 16;
        if (row >= M) continue;
#pragma unroll
        for (int j = 0; j < 8; j++) {
            int col = tx + j * 16;
            float v = acc[i][j] + bias[col];
            v = fmaxf(v, 0.0f);
            if (MODE == 2) v += p1[(size_t)row * HDIM + col];  // ha = battr + relu(eta)
            out[(size_t)row * HDIM + col] = v;
        }
    }
}

// ---------------------------------------------------------------------------
// Line-graph aggregation: agg[btgt] += he0[bsrc] * bond_edge_attr
// ---------------------------------------------------------------------------
__global__ void scatter_line_kernel(const int* __restrict__ bidx,
                                    const float* __restrict__ battr, int E2) {
    int e = blockIdx.x;
    int d = threadIdx.x;
    int bs = bidx[e];
    int bt = bidx[(size_t)E2 + e];
    float v = g_he0[(size_t)bs * HDIM + d] * battr[(size_t)e * HDIM + d];
    atomicAdd(&g_agg[(size_t)bt * HDIM + d], v);
}

// ---------------------------------------------------------------------------
// Attention pass 1: beta[e,h] = leaky_relu(dot) ; segment max over tgt
// 128 threads: 16 edges x 8 heads
// ---------------------------------------------------------------------------
__global__ void attn_beta_kernel(const float* __restrict__ x, const int* __restrict__ eidx,
                                 const float* __restrict__ he, const float* __restrict__ attw,
                                 const float* __restrict__ attb, int E) {
    int t = threadIdx.x;
    int e = blockIdx.x * 16 + (t >> 3);
    int h = t & 7;
    if (e >= E) return;
    int s = eidx[e];
    int g = eidx[(size_t)E + e];
    const float4* xs = reinterpret_cast<const float4*>(x + (size_t)s * HDIM + h * DHEAD);
    const float4* xt = reinterpret_cast<const float4*>(x + (size_t)g * HDIM + h * DHEAD);
    const float4* hp = reinterpret_cast<const float4*>(he + (size_t)e * HDIM + h * DHEAD);
    const float4* w1 = reinterpret_cast<const float4*>(attw);
    const float4* w2 = reinterpret_cast<const float4*>(attw + DHEAD);
    float acc = attb[0];
#pragma unroll
    for (int i = 0; i < 4; i++) {
        float4 a = xs[i], hh = hp[i], b = xt[i], u = w1[i], v = w2[i];
        acc += (a.x * hh.x) * u.x + (a.y * hh.y) * u.y + (a.z * hh.z) * u.z + (a.w * hh.w) * u.w;
        acc += b.x * v.x + b.y * v.y + b.z * v.z + b.w * v.w;
    }
    float beta = (acc > 0.0f) ? acc : 0.01f * acc;  // leaky_relu 0.01
    g_beta[(size_t)e * NHEAD + h] = beta;
    atomicMax(&g_max[(size_t)g * NHEAD + h], encf(beta));
}

// ---------------------------------------------------------------------------
// Attention pass 2: ex = exp(beta - m[tgt]); den[tgt] += ex
// ---------------------------------------------------------------------------
__global__ void attn_exp_kernel(const int* __restrict__ eidx, int E) {
    int i = blockIdx.x * blockDim.x + threadIdx.x;
    if (i >= E * NHEAD) return;
    int e = i >> 3;
    int h = i & 7;
    int g = eidx[(size_t)E + e];
    float m = decf(g_max[(size_t)g * NHEAD + h]);
    float ex = expf(g_beta[i] - m);
    g_beta[i] = ex;
    atomicAdd(&g_den[(size_t)g * NHEAD + h], ex);
}

// ---------------------------------------------------------------------------
// Attention pass 3: agg2[tgt] += alpha * x[src] * he[e]
// ---------------------------------------------------------------------------
__global__ void attn_scatter_kernel(const float* __restrict__ x, const int* __restrict__ eidx,
                                    const float* __restrict__ he, int E) {
    int e = blockIdx.x;
    int d = threadIdx.x;
    int s = eidx[e];
    int g = eidx[(size_t)E + e];
    int h = d >> 4;
    float den = g_den[(size_t)g * NHEAD + h];
    float alpha = g_beta[(size_t)e * NHEAD + h] / (den + 1e-16f);
    float v = alpha * x[(size_t)s * HDIM + d] * he[(size_t)e * HDIM + d];
    atomicAdd(&g_agg2[(size_t)g * HDIM + d], v);
}

// ---------------------------------------------------------------------------
// Launch
// ---------------------------------------------------------------------------
extern "C" void kernel_launch(void* const* d_in, const int* in_sizes, int n_in,
                              void* d_out, int out_size) {
    const float* x     = (const float*)d_in[0];
    const int*   eidx  = (const int*)d_in[1];     // int32! (JAX x64 disabled)
    const float* eattr = (const float*)d_in[2];
    const int*   bidx  = (const int*)d_in[3];     // int32!
    const float* battr = (const float*)d_in[4];
    const float* Wn2e  = (const float*)d_in[5];
    const float* bn2e  = (const float*)d_in[6];
    const float* A1w   = (const float*)d_in[7];
    const float* A1b   = (const float*)d_in[8];
    const float* A2w   = (const float*)d_in[9];
    const float* A2b   = (const float*)d_in[10];
    const float* A3w   = (const float*)d_in[11];
    const float* A3b   = (const float*)d_in[12];
    const float* Wc1w  = (const float*)d_in[13];
    const float* Wc1b  = (const float*)d_in[14];
    const float* attw  = (const float*)d_in[15];
    const float* attb  = (const float*)d_in[16];
    const float* Wc2w  = (const float*)d_in[17];
    const float* Wc2b  = (const float*)d_in[18];

    const int N  = in_sizes[0] / HDIM;
    const int E  = in_sizes[1] / 2;
    const int E2 = in_sizes[3] / 2;

    float* out    = (float*)d_out;
    float* out_hx = out;                              // [N, H]
    float* out_he = out + (size_t)N * HDIM;           // [E, H]
    float* out_ha = out_he + (size_t)E * HDIM;        // [E2, H]

    // Device pointers to scratch symbols
    void *p_he0, *p_agg, *p_agg2, *p_den, *p_max, *p_wcomb, *p_bcomb;
    cudaGetSymbolAddress(&p_he0, g_he0);
    cudaGetSymbolAddress(&p_agg, g_agg);
    cudaGetSymbolAddress(&p_agg2, g_agg2);
    cudaGetSymbolAddress(&p_den, g_den);
    cudaGetSymbolAddress(&p_max, g_max);
    cudaGetSymbolAddress(&p_wcomb, g_wcomb);
    cudaGetSymbolAddress(&p_bcomb, g_bcomb);

    // Zero accumulators (memset 0x00 is valid identity under encf ordering for g_max)
    cudaMemsetAsync(p_agg, 0, (size_t)E * HDIM * sizeof(float), 0);
    cudaMemsetAsync(p_agg2, 0, (size_t)N * HDIM * sizeof(float), 0);
    cudaMemsetAsync(p_den, 0, (size_t)N * NHEAD * sizeof(float), 0);
    cudaMemsetAsync(p_max, 0, (size_t)N * NHEAD * sizeof(unsigned), 0);

    // Pack eta weights
    prep_kernel<<<(128 * 128 + 255) / 256, 256>>>(A1w, A2w, A3w, A1b, A2b, A3b);

    // he0 = relu([x[src], x[tgt], eattr] @ W_n2e + b)
    gemm_kernel<0, 384><<<(E + 63) / 64, 256>>>(x, eattr, eidx, Wn2e, bn2e, (float*)p_he0, E);

    // agg = segment_sum(he0[bsrc] * battr, btgt)
    scatter_line_kernel<<<E2, HDIM>>>(bidx, battr, E2);

    // he = relu([he0, agg] @ Wc1 + b)
    gemm_kernel<1, 256><<<(E + 63) / 64, 256>>>((const float*)p_he0, (const float*)p_agg,
                                                nullptr, Wc1w, Wc1b, out_he, E);

    // ha = battr + relu(he0[bsrc]@A1 + he0[btgt]@A2 + battr@A3 + b1+b2+b3)
    gemm_kernel<2, 384><<<(E2 + 63) / 64, 256>>>((const float*)p_he0, battr, bidx,
                                                 (const float*)p_wcomb, (const float*)p_bcomb,
                                                 out_ha, E2);

    // Attention
    attn_beta_kernel<<<(E + 15) / 16, 128>>>(x, eidx, out_he, attw, attb, E);
    attn_exp_kernel<<<(E * NHEAD + 255) / 256, 256>>>(eidx, E);
    attn_scatter_kernel<<<E, HDIM>>>(x, eidx, out_he, E);

    // hx = relu([x, agg2] @ Wc2 + b)
    gemm_kernel<3, 256><<<(N + 63) / 64, 256>>>(x, (const float*)p_agg2, nullptr,
                                                Wc2w, Wc2b, out_hx, N);
}

// round 3
// speedup vs baseline: 1.4975x; 1.4975x over previous
#include <cuda_runtime.h>
#include <cstdint>
#include <cstdio>
#include <cstring>

// Problem constants (fixed by the dataset)
#define HDIM 128
#define NHEAD 8
#define DHEAD 16
#define N_NODES 50000
#define E_EDGES 600000
#define E2_EDGES 600000

// ---------------------------------------------------------------------------
// Scratch (device globals — no allocation allowed)
// ---------------------------------------------------------------------------
__device__ __align__(16) float    g_he0[(size_t)E_EDGES * HDIM];    // 307 MB
__device__ __align__(16) float    g_agg[(size_t)E_EDGES * HDIM];    // 307 MB
__device__ __align__(16) float    g_q1[(size_t)N_NODES * HDIM];     // 25.6 MB
__device__ __align__(16) float    g_q2[(size_t)N_NODES * HDIM];     // 25.6 MB
__device__ float    g_beta[(size_t)E_EDGES * NHEAD];  // beta, then ex
__device__ unsigned g_max[(size_t)N_NODES * NHEAD];   // encoded float max
__device__ float    g_den[(size_t)N_NODES * NHEAD];
__device__ __align__(16) float    g_agg2[(size_t)N_NODES * HDIM];
__device__ __align__(16) float    g_wcomb[384 * 128];               // [A1;A2;A3]
__device__ __align__(16) float    g_bcomb[128];                     // b1+b2+b3

// ---------------------------------------------------------------------------
// Monotone float<->uint encoding for atomicMax on floats (memset-0 = identity)
// ---------------------------------------------------------------------------
__device__ __forceinline__ unsigned encf(float f) {
    int i = __float_as_int(f);
    return (i >= 0) ? ((unsigned)i | 0x80000000u) : ~(unsigned)i;
}
__device__ __forceinline__ float decf(unsigned u) {
    int i = (u & 0x80000000u) ? (int)(u & 0x7FFFFFFFu) : (int)(~u);
    return __int_as_float(i);
}

// ---------------------------------------------------------------------------
// Packed f32x2 helpers (Blackwell: fma.rn.f32x2 — 2 FMAs per issue slot)
// ---------------------------------------------------------------------------
__device__ __forceinline__ unsigned long long pk2(float lo, float hi) {
    unsigned long long r;
    asm("mov.b64 %0, {%1, %2};" : "=l"(r) : "f"(lo), "f"(hi));
    return r;
}
__device__ __forceinline__ void upk2(unsigned long long v, float& lo, float& hi) {
    asm("mov.b64 {%0, %1}, %2;" : "=f"(lo), "=f"(hi) : "l"(v));
}
__device__ __forceinline__ void fma2(unsigned long long& acc, unsigned long long a,
                                     unsigned long long b) {
    asm("fma.rn.f32x2 %0, %1, %2, %0;" : "+l"(acc) : "l"(a), "l"(b));
}
__device__ __forceinline__ unsigned long long f2_as_u64(float2 v) {
    unsigned long long r;
    asm("mov.b64 %0, {%1, %2};" : "=l"(r) : "f"(v.x), "f"(v.y));
    return r;
}

// ---------------------------------------------------------------------------
// Pre-pack eta weights: g_wcomb = [A1_w; A2_w; A3_w], g_bcomb = b1+b2+b3
// ---------------------------------------------------------------------------
__global__ void prep_kernel(const float* __restrict__ A1w, const float* __restrict__ A2w,
                            const float* __restrict__ A3w, const float* __restrict__ b1,
                            const float* __restrict__ b2, const float* __restrict__ b3) {
    int i = blockIdx.x * blockDim.x + threadIdx.x;
    if (i < 128 * 128) {
        g_wcomb[i]                 = A1w[i];
        g_wcomb[128 * 128 + i]     = A2w[i];
        g_wcomb[2 * 128 * 128 + i] = A3w[i];
    }
    if (i < 128) g_bcomb[i] = b1[i] + b2[i] + b3[i];
}

// ---------------------------------------------------------------------------
// FFMA2 gather-SGEMM.  BM=128, BN=128, BK=8, 256 threads, 8x8 per thread.
//   MODE 0: A = eattr (dense, K=128), epi = relu(acc + bias + q1[i0] + q2[i1]) -> he0
//   MODE 1: A = [p0[row], p1[row]]  (dense, K=256), epi = relu(acc + bias)
//   MODE 2: A = [p0[i0], p0[i1], p1[row]] (gather, K=384), epi = relu(acc+bias) + p1[row]
//   MODE 4: A = p0 (dense, K=128), epi = raw store (no bias)
// ---------------------------------------------------------------------------
template <int MODE, int K>
__global__ void __launch_bounds__(256, 2)
gemm2_kernel(const float* __restrict__ p0, const float* __restrict__ p1,
             const float* __restrict__ q2, const int* __restrict__ idx,
             const float* __restrict__ W, const float* __restrict__ bias,
             float* __restrict__ out, int M) {
    __shared__ float As[8][130];   // pad 130: conflict-free + 8B-aligned float2 rows
    __shared__ float Bs[8][128];
    __shared__ int   s_i0[128];
    __shared__ int   s_i1[128];

    const int tid = threadIdx.x;
    const int tx = tid & 15;    // N: col pairs at 2*tx + 32*q
    const int ty = tid >> 4;    // M: row pairs at 2*ty + 32*p
    const int m0 = blockIdx.x * 128;

    if (MODE == 0 || MODE == 2) {
        if (tid < 128) {
            int r = m0 + tid;
            if (r < M) s_i0[tid] = idx[r];
        } else {
            int t = tid - 128;
            int r = m0 + t;
            if (r < M) s_i1[t] = idx[(size_t)M + r];
        }
        __syncthreads();
    }

    unsigned long long acc[8][4];
#pragma unroll
    for (int i = 0; i < 8; i++)
#pragma unroll
        for (int j = 0; j < 4; j++) acc[i][j] = 0ull;

    const int a_row = tid >> 1;
    const int a_kk  = (tid & 1) * 4;
    const float4* Wf4 = reinterpret_cast<const float4*>(W);

    for (int k0 = 0; k0 < K; k0 += 8) {
        // ---- A tile: 128 rows x 8 k = 256 float4 loads (1 per thread) ----
        {
            int gk = k0 + a_kk;
            int r = m0 + a_row;
            float4 v = make_float4(0.f, 0.f, 0.f, 0.f);
            if (r < M) {
                const float* base;
                if (MODE == 2) {
                    int seg = gk >> 7;
                    int col = gk & 127;
                    base = (seg == 0) ? p0 + (size_t)s_i0[a_row] * HDIM + col
                         : (seg == 1) ? p0 + (size_t)s_i1[a_row] * HDIM + col
                                      : p1 + (size_t)r * HDIM + col;
                } else if (MODE == 1) {
                    int seg = gk >> 7;
                    int col = gk & 127;
                    base = ((seg == 0) ? p0 : p1) + (size_t)r * HDIM + col;
                } else {  // MODE 0, 4: dense K=128
                    base = p0 + (size_t)r * HDIM + gk;
                }
                v = *reinterpret_cast<const float4*>(base);
            }
            As[a_kk + 0][a_row] = v.x;
            As[a_kk + 1][a_row] = v.y;
            As[a_kk + 2][a_row] = v.z;
            As[a_kk + 3][a_row] = v.w;
        }
        // ---- B tile: 8 x 128 = 256 float4 (1 per thread) ----
        reinterpret_cast<float4*>(&Bs[0][0])[tid] = Wf4[k0 * 32 + tid];
        __syncthreads();

#pragma unroll
        for (int k = 0; k < 8; k++) {
            float2 a2[4];
            unsigned long long bb[4];
#pragma unroll
            for (int p = 0; p < 4; p++)
                a2[p] = *reinterpret_cast<const float2*>(&As[k][2 * ty + 32 * p]);
#pragma unroll
            for (int q = 0; q < 4; q++)
                bb[q] = f2_as_u64(*reinterpret_cast<const float2*>(&Bs[k][2 * tx + 32 * q]));
#pragma unroll
            for (int p = 0; p < 4; p++) {
                unsigned long long alo = pk2(a2[p].x, a2[p].x);
                unsigned long long ahi = pk2(a2[p].y, a2[p].y);
#pragma unroll
                for (int q = 0; q < 4; q++) fma2(acc[2 * p + 0][q], alo, bb[q]);
#pragma unroll
                for (int q = 0; q < 4; q++) fma2(acc[2 * p + 1][q], ahi, bb[q]);
            }
        }
        __syncthreads();
    }

    // ---- Epilogue ----
#pragma unroll
    for (int r8 = 0; r8 < 8; r8++) {
        int p = r8 >> 1, sub = r8 & 1;
        int rl = 32 * p + 2 * ty + sub;
        int row = m0 + rl;
        if (row >= M) continue;
#pragma unroll
        for (int q = 0; q < 4; q++) {
            int col = 32 * q + 2 * tx;
            float cx, cy;
            upk2(acc[r8][q], cx, cy);
            if (MODE == 4) {
                float2 st = make_float2(cx, cy);
                *reinterpret_cast<float2*>(&out[(size_t)row * HDIM + col]) = st;
                continue;
            }
            float2 bs = *reinterpret_cast<const float2*>(&bias[col]);
            cx += bs.x; cy += bs.y;
            if (MODE == 0) {
                float2 qa = *reinterpret_cast<const float2*>(&p1[(size_t)s_i0[rl] * HDIM + col]);
                float2 qb = *reinterpret_cast<const float2*>(&q2[(size_t)s_i1[rl] * HDIM + col]);
                cx += qa.x + qb.x;
                cy += qa.y + qb.y;
            }
            cx = fmaxf(cx, 0.0f);
            cy = fmaxf(cy, 0.0f);
            if (MODE == 2) {
                float2 ba = *reinterpret_cast<const float2*>(&p1[(size_t)row * HDIM + col]);
                cx += ba.x; cy += ba.y;
            }
            float2 st = make_float2(cx, cy);
            *reinterpret_cast<float2*>(&out[(size_t)row * HDIM + col]) = st;
        }
    }
}

// ---------------------------------------------------------------------------
// Line-graph aggregation: agg[btgt] += he0[bsrc] * bond_edge_attr
// ---------------------------------------------------------------------------
__global__ void scatter_line_kernel(const int* __restrict__ bidx,
                                    const float* __restrict__ battr, int E2) {
    int e = blockIdx.x;
    int d = threadIdx.x;
    int bs = bidx[e];
    int bt = bidx[(size_t)E2 + e];
    float v = g_he0[(size_t)bs * HDIM + d] * battr[(size_t)e * HDIM + d];
    atomicAdd(&g_agg[(size_t)bt * HDIM + d], v);
}

// ---------------------------------------------------------------------------
// Attention pass 1: beta[e,h] = leaky_relu(dot) ; segment max over tgt
// ---------------------------------------------------------------------------
__global__ void attn_beta_kernel(const float* __restrict__ x, const int* __restrict__ eidx,
                                 const float* __restrict__ he, const float* __restrict__ attw,
                                 const float* __restrict__ attb, int E) {
    int t = threadIdx.x;
    int e = blockIdx.x * 16 + (t >> 3);
    int h = t & 7;
    if (e >= E) return;
    int s = eidx[e];
    int g = eidx[(size_t)E + e];
    const float4* xs = reinterpret_cast<const float4*>(x + (size_t)s * HDIM + h * DHEAD);
    const float4* xt = reinterpret_cast<const float4*>(x + (size_t)g * HDIM + h * DHEAD);
    const float4* hp = reinterpret_cast<const float4*>(he + (size_t)e * HDIM + h * DHEAD);
    const float4* w1 = reinterpret_cast<const float4*>(attw);
    const float4* w2 = reinterpret_cast<const float4*>(attw + DHEAD);
    float acc = attb[0];
#pragma unroll
    for (int i = 0; i < 4; i++) {
        float4 a = xs[i], hh = hp[i], b = xt[i], u = w1[i], v = w2[i];
        acc += (a.x * hh.x) * u.x + (a.y * hh.y) * u.y + (a.z * hh.z) * u.z + (a.w * hh.w) * u.w;
        acc += b.x * v.x + b.y * v.y + b.z * v.z + b.w * v.w;
    }
    float beta = (acc > 0.0f) ? acc : 0.01f * acc;  // leaky_relu 0.01
    g_beta[(size_t)e * NHEAD + h] = beta;
    atomicMax(&g_max[(size_t)g * NHEAD + h], encf(beta));
}

// ---------------------------------------------------------------------------
// Attention pass 2: ex = exp(beta - m[tgt]); den[tgt] += ex
// ---------------------------------------------------------------------------
__global__ void attn_exp_kernel(const int* __restrict__ eidx, int E) {
    int i = blockIdx.x * blockDim.x + threadIdx.x;
    if (i >= E * NHEAD) return;
    int e = i >> 3;
    int h = i & 7;
    int g = eidx[(size_t)E + e];
    float m = decf(g_max[(size_t)g * NHEAD + h]);
    float ex = expf(g_beta[i] - m);
    g_beta[i] = ex;
    atomicAdd(&g_den[(size_t)g * NHEAD + h], ex);
}

// ---------------------------------------------------------------------------
// Attention pass 3: agg2[tgt] += alpha * x[src] * he[e]
// ---------------------------------------------------------------------------
__global__ void attn_scatter_kernel(const float* __restrict__ x, const int* __restrict__ eidx,
                                    const float* __restrict__ he, int E) {
    int e = blockIdx.x;
    int d = threadIdx.x;
    int s = eidx[e];
    int g = eidx[(size_t)E + e];
    int h = d >> 4;
    float den = g_den[(size_t)g * NHEAD + h];
    float alpha = g_beta[(size_t)e * NHEAD + h] / (den + 1e-16f);
    float v = alpha * x[(size_t)s * HDIM + d] * he[(size_t)e * HDIM + d];
    atomicAdd(&g_agg2[(size_t)g * HDIM + d], v);
}

// ---------------------------------------------------------------------------
// Launch
// ---------------------------------------------------------------------------
extern "C" void kernel_launch(void* const* d_in, const int* in_sizes, int n_in,
                              void* d_out, int out_size) {
    const float* x     = (const float*)d_in[0];
    const int*   eidx  = (const int*)d_in[1];     // int32 (JAX x64 disabled)
    const float* eattr = (const float*)d_in[2];
    const int*   bidx  = (const int*)d_in[3];
    const float* battr = (const float*)d_in[4];
    const float* Wn2e  = (const float*)d_in[5];
    const float* bn2e  = (const float*)d_in[6];
    const float* A1w   = (const float*)d_in[7];
    const float* A1b   = (const float*)d_in[8];
    const float* A2w   = (const float*)d_in[9];
    const float* A2b   = (const float*)d_in[10];
    const float* A3w   = (const float*)d_in[11];
    const float* A3b   = (const float*)d_in[12];
    const float* Wc1w  = (const float*)d_in[13];
    const float* Wc1b  = (const float*)d_in[14];
    const float* attw  = (const float*)d_in[15];
    const float* attb  = (const float*)d_in[16];
    const float* Wc2w  = (const float*)d_in[17];
    const float* Wc2b  = (const float*)d_in[18];

    const int N  = in_sizes[0] / HDIM;
    const int E  = in_sizes[1] / 2;
    const int E2 = in_sizes[3] / 2;

    float* out    = (float*)d_out;
    float* out_hx = out;                              // [N, H]
    float* out_he = out + (size_t)N * HDIM;           // [E, H]
    float* out_ha = out_he + (size_t)E * HDIM;        // [E2, H]

    // Device pointers to scratch symbols
    void *p_he0, *p_agg, *p_agg2, *p_den, *p_max, *p_wcomb, *p_bcomb, *p_q1, *p_q2;
    cudaGetSymbolAddress(&p_he0, g_he0);
    cudaGetSymbolAddress(&p_agg, g_agg);
    cudaGetSymbolAddress(&p_agg2, g_agg2);
    cudaGetSymbolAddress(&p_den, g_den);
    cudaGetSymbolAddress(&p_max, g_max);
    cudaGetSymbolAddress(&p_wcomb, g_wcomb);
    cudaGetSymbolAddress(&p_bcomb, g_bcomb);
    cudaGetSymbolAddress(&p_q1, g_q1);
    cudaGetSymbolAddress(&p_q2, g_q2);

    // Zero accumulators (0x00 is the identity under encf ordering for g_max)
    cudaMemsetAsync(p_agg, 0, (size_t)E * HDIM * sizeof(float), 0);
    cudaMemsetAsync(p_agg2, 0, (size_t)N * HDIM * sizeof(float), 0);
    cudaMemsetAsync(p_den, 0, (size_t)N * NHEAD * sizeof(float), 0);
    cudaMemsetAsync(p_max, 0, (size_t)N * NHEAD * sizeof(unsigned), 0);

    prep_kernel<<<(128 * 128 + 255) / 256, 256>>>(A1w, A2w, A3w, A1b, A2b, A3b);

    const int gN = (N + 127) / 128;
    const int gE = (E + 127) / 128;
    const int gE2 = (E2 + 127) / 128;

    // Q1 = x @ W1, Q2 = x @ W2 (N-sized dense GEMMs, raw store)
    gemm2_kernel<4, 128><<<gN, 256>>>(x, nullptr, nullptr, nullptr,
                                      Wn2e, nullptr, (float*)p_q1, N);
    gemm2_kernel<4, 128><<<gN, 256>>>(x, nullptr, nullptr, nullptr,
                                      Wn2e + 128 * 128, nullptr, (float*)p_q2, N);

    // he0 = relu(eattr @ W3 + Q1[src] + Q2[tgt] + b)
    gemm2_kernel<0, 128><<<gE, 256>>>(eattr, (const float*)p_q1, (const float*)p_q2, eidx,
                                      Wn2e + 2 * 128 * 128, bn2e, (float*)p_he0, E);

    // agg = segment_sum(he0[bsrc] * battr, btgt)
    scatter_line_kernel<<<E2, HDIM>>>(bidx, battr, E2);

    // he = relu([he0, agg] @ Wc1 + b)
    gemm2_kernel<1, 256><<<gE, 256>>>((const float*)p_he0, (const float*)p_agg, nullptr,
                                      nullptr, Wc1w, Wc1b, out_he, E);

    // ha = battr + relu(he0[bsrc]@A1 + he0[btgt]@A2 + battr@A3 + bcomb)
    gemm2_kernel<2, 384><<<gE2, 256>>>((const float*)p_he0, battr, nullptr, bidx,
                                       (const float*)p_wcomb, (const float*)p_bcomb,
                                       out_ha, E2);

    // Attention
    attn_beta_kernel<<<(E + 15) / 16, 128>>>(x, eidx, out_he, attw, attb, E);
    attn_exp_kernel<<<(E * NHEAD + 255) / 256, 256>>>(eidx, E);
    attn_scatter_kernel<<<E, HDIM>>>(x, eidx, out_he, E);

    // hx = relu([x, agg2] @ Wc2 + b)
    gemm2_kernel<1, 256><<<gN, 256>>>(x, (const float*)p_agg2, nullptr, nullptr,
                                      Wc2w, Wc2b, out_hx, N);
}

// round 5
// speedup vs baseline: 2.4720x; 1.6508x over previous
#include <cuda_runtime.h>
#include <cstdint>
#include <cstdio>

// Problem constants (fixed by the dataset)
#define HDIM 128
#define NHEAD 8
#define DHEAD 16
#define N_NODES 50000
#define E_EDGES 600000
#define E2_EDGES 600000

// ===========================================================================
// Scratch (device globals — no allocation allowed)
// ===========================================================================
__device__ __align__(16) float    g_he0[(size_t)E_EDGES * HDIM];
__device__ __align__(16) float    g_agg[(size_t)E_EDGES * HDIM];
__device__ __align__(16) float    g_q1[(size_t)N_NODES * HDIM];
__device__ __align__(16) float    g_q2[(size_t)N_NODES * HDIM];
__device__ float    g_beta[(size_t)E_EDGES * NHEAD];
__device__ unsigned g_max[(size_t)N_NODES * NHEAD];
__device__ float    g_den[(size_t)N_NODES * NHEAD];
__device__ __align__(16) float    g_agg2[(size_t)N_NODES * HDIM];
__device__ __align__(16) float    g_bt[40 * 4096];   // tf32-converted weights
__device__ __align__(16) float    g_bcomb[128];      // b1+b2+b3

// Offsets in g_bt (floats)
#define BT_W1   0
#define BT_W2   16384
#define BT_W3   32768
#define BT_WC1  49152
#define BT_COMB 81920
#define BT_WC2  131072

// ===========================================================================
// Helpers
// ===========================================================================
__device__ __forceinline__ unsigned encf(float f) {
    int i = __float_as_int(f);
    return (i >= 0) ? ((unsigned)i | 0x80000000u) : ~(unsigned)i;
}
__device__ __forceinline__ float decf(unsigned u) {
    int i = (u & 0x80000000u) ? (int)(u & 0x7FFFFFFFu) : (int)(~u);
    return __int_as_float(i);
}
__device__ __forceinline__ uint32_t to_tf32(float f) {
    uint32_t r;
    asm("cvt.rna.tf32.f32 %0, %1;" : "=r"(r) : "f"(f));
    return r;
}
__device__ __forceinline__ void mma_tf32(float (&d)[4], const uint32_t (&a)[4],
                                         uint32_t b0, uint32_t b1) {
    asm volatile(
        "mma.sync.aligned.m16n8k8.row.col.f32.tf32.tf32.f32 "
        "{%0,%1,%2,%3}, {%4,%5,%6,%7}, {%8,%9}, {%0,%1,%2,%3};"
        : "+f"(d[0]), "+f"(d[1]), "+f"(d[2]), "+f"(d[3])
        : "r"(a[0]), "r"(a[1]), "r"(a[2]), "r"(a[3]), "r"(b0), "r"(b1));
}

// ===========================================================================
// prep: elementwise tf32 conversion of weights
// ===========================================================================
__global__ void prep_tf32_kernel(const float* __restrict__ src, float* __restrict__ dst,
                                 int count) {
    int i = blockIdx.x * blockDim.x + threadIdx.x;
    if (i < count) dst[i] = __uint_as_float(to_tf32(src[i]));
}
__global__ void prep_bias_kernel(const float* __restrict__ b1, const float* __restrict__ b2,
                                 const float* __restrict__ b3) {
    int i = threadIdx.x;
    if (i < 128) g_bcomb[i] = b1[i] + b2[i] + b3[i];
}

// ===========================================================================
// mma.sync tf32 gather-GEMM.  C[128,128] = epi(A @ W + bias)
//   MODE 0: A = eattr (K=128), epi = relu(acc + bias + q1[i0] + q2[i1])
//   MODE 1: A = [p0[row], p1[row]] (K=256), epi = relu(acc + bias)
//   MODE 2: A = [p0[i0], p0[i1], p1[row]] (K=384), epi = relu(acc+bias) + p1[row]
//   MODE 4: A = p0 (K=128), epi = raw store
// 256 threads, 8 warps (4M x 2N), warp tile 32x64, m16n8k8 tf32.
// ===========================================================================
template <int MODE, int K>
__global__ void __launch_bounds__(256, 2)
mma_gemm(const float* __restrict__ p0, const float* __restrict__ p1,
         const float* __restrict__ q2g, const int* __restrict__ idx,
         const float* __restrict__ Bt, const float* __restrict__ bias,
         float* __restrict__ out, int M) {
    __shared__ float As[2][128][20];   // stride 20: conflict-free fragment loads
    __shared__ float Bs[2][16][136];   // stride 136: conflict-free fragment loads
    __shared__ float s_bias[128];
    __shared__ int   s_i0[128];
    __shared__ int   s_i1[128];

    const int tid  = threadIdx.x;
    const int wid  = tid >> 5;
    const int lane = tid & 31;
    const int wm   = wid >> 1;      // 0..3  (M tile: rows wm*32)
    const int wn   = wid & 1;       // 0..1  (N tile: cols wn*64)
    const int m0   = blockIdx.x * 128;

    if (MODE == 0 || MODE == 2) {
        if (tid < 128) {
            int r = m0 + tid;
            s_i0[tid] = (r < M) ? idx[r] : 0;
        } else {
            int t = tid - 128;
            int r = m0 + t;
            s_i1[t] = (r < M) ? idx[(size_t)M + r] : 0;
        }
    }
    if (MODE != 4 && tid < 128) s_bias[tid] = bias[tid];
    __syncthreads();

    float acc[2][8][4];
#pragma unroll
    for (int t = 0; t < 2; t++)
#pragma unroll
        for (int n = 0; n < 8; n++)
#pragma unroll
            for (int j = 0; j < 4; j++) acc[t][n][j] = 0.0f;

    float4 stA[2], stB[2];

    // ---- fetch chunk c (global -> regs) ----
    auto fetch = [&](int c) {
        const int kbase = c * 16;
#pragma unroll
        for (int i = 0; i < 2; i++) {
            int f = tid + i * 256;          // 0..511
            int row = f >> 2;
            int k4 = (f & 3) * 4;
            float4 v = make_float4(0.f, 0.f, 0.f, 0.f);
            int r = m0 + row;
            if (r < M) {
                const float* src;
                if (MODE == 2) {
                    int seg = kbase >> 7;
                    int col = (kbase & 127) + k4;
                    src = (seg == 0) ? p0 + (size_t)s_i0[row] * HDIM + col
                        : (seg == 1) ? p0 + (size_t)s_i1[row] * HDIM + col
                                     : p1 + (size_t)r * HDIM + col;
                } else if (MODE == 1) {
                    int seg = kbase >> 7;
                    int col = (kbase & 127) + k4;
                    src = ((seg == 0) ? p0 : p1) + (size_t)r * HDIM + col;
                } else {
                    src = p0 + (size_t)r * HDIM + kbase + k4;
                }
                v = *reinterpret_cast<const float4*>(src);
            }
            stA[i] = v;
        }
#pragma unroll
        for (int i = 0; i < 2; i++) {
            int f = tid + i * 256;
            int k = f >> 5;
            int nf = (f & 31) * 4;
            stB[i] = *reinterpret_cast<const float4*>(Bt + (size_t)(kbase + k) * 128 + nf);
        }
    };
    // ---- commit staged regs -> smem buffer b (A converted to tf32) ----
    auto commit = [&](int b) {
#pragma unroll
        for (int i = 0; i < 2; i++) {
            int f = tid + i * 256;
            int row = f >> 2;
            int k4 = (f & 3) * 4;
            As[b][row][k4 + 0] = __uint_as_float(to_tf32(stA[i].x));
            As[b][row][k4 + 1] = __uint_as_float(to_tf32(stA[i].y));
            As[b][row][k4 + 2] = __uint_as_float(to_tf32(stA[i].z));
            As[b][row][k4 + 3] = __uint_as_float(to_tf32(stA[i].w));
        }
#pragma unroll
        for (int i = 0; i < 2; i++) {
            int f = tid + i * 256;
            int k = f >> 5;
            int nf = (f & 31) * 4;
            *reinterpret_cast<float4*>(&Bs[b][k][nf]) = stB[i];
        }
    };

    fetch(0);
    commit(0);
    __syncthreads();

    constexpr int NC = K / 16;
    const int arow = lane >> 2;
    const int acol = lane & 3;

    for (int c = 0; c < NC; c++) {
        int b = c & 1;
        if (c + 1 < NC) fetch(c + 1);
#pragma unroll
        for (int ks = 0; ks < 2; ks++) {
            int k0 = ks * 8;
            uint32_t a[2][4];
#pragma unroll
            for (int t = 0; t < 2; t++) {
                int rb = wm * 32 + t * 16 + arow;
                a[t][0] = __float_as_uint(As[b][rb][k0 + acol]);
                a[t][1] = __float_as_uint(As[b][rb + 8][k0 + acol]);
                a[t][2] = __float_as_uint(As[b][rb][k0 + acol + 4]);
                a[t][3] = __float_as_uint(As[b][rb + 8][k0 + acol + 4]);
            }
#pragma unroll
            for (int nt = 0; nt < 8; nt++) {
                int nb = wn * 64 + nt * 8 + arow;
                uint32_t b0 = __float_as_uint(Bs[b][k0 + acol][nb]);
                uint32_t b1 = __float_as_uint(Bs[b][k0 + 4 + acol][nb]);
                mma_tf32(acc[0][nt], a[0], b0, b1);
                mma_tf32(acc[1][nt], a[1], b0, b1);
            }
        }
        __syncthreads();
        if (c + 1 < NC) {
            commit(b ^ 1);
            __syncthreads();
        }
    }

    // ---- Epilogue: fragment layout -> fused float2 stores ----
    const int acol2 = (lane & 3) * 2;
#pragma unroll
    for (int t = 0; t < 2; t++) {
        int rl0 = wm * 32 + t * 16 + arow;       // local row of d0/d1
#pragma unroll
        for (int nt = 0; nt < 8; nt++) {
            int col = wn * 64 + nt * 8 + acol2;
#pragma unroll
            for (int half = 0; half < 2; half++) {
                int rl = rl0 + half * 8;
                int grow = m0 + rl;
                if (grow >= M) continue;
                float v0 = acc[t][nt][half * 2 + 0];
                float v1 = acc[t][nt][half * 2 + 1];
                if (MODE != 4) {
                    v0 += s_bias[col];
                    v1 += s_bias[col + 1];
                    if (MODE == 0) {
                        const float* q1p = p1 + (size_t)s_i0[rl] * HDIM + col;
                        const float* q2p = q2g + (size_t)s_i1[rl] * HDIM + col;
                        v0 += q1p[0] + q2p[0];
                        v1 += q1p[1] + q2p[1];
                    }
                    v0 = fmaxf(v0, 0.0f);
                    v1 = fmaxf(v1, 0.0f);
                    if (MODE == 2) {
                        const float* bp = p1 + (size_t)grow * HDIM + col;
                        v0 += bp[0];
                        v1 += bp[1];
                    }
                }
                *reinterpret_cast<float2*>(out + (size_t)grow * HDIM + col) =
                    make_float2(v0, v1);
            }
        }
    }
}

// ===========================================================================
// Line-graph aggregation: agg[btgt] += he0[bsrc] * bond_edge_attr
// ===========================================================================
__global__ void scatter_line_kernel(const int* __restrict__ bidx,
                                    const float* __restrict__ battr, int E2) {
    int e = blockIdx.x;
    int d = threadIdx.x;
    int bs = bidx[e];
    int bt = bidx[(size_t)E2 + e];
    float v = g_he0[(size_t)bs * HDIM + d] * battr[(size_t)e * HDIM + d];
    atomicAdd(&g_agg[(size_t)bt * HDIM + d], v);
}

// ===========================================================================
// Attention pass 1: beta[e,h] = leaky_relu(dot); segment max over tgt
// ===========================================================================
__global__ void attn_beta_kernel(const float* __restrict__ x, const int* __restrict__ eidx,
                                 const float* __restrict__ he, const float* __restrict__ attw,
                                 const float* __restrict__ attb, int E) {
    int t = threadIdx.x;
    int e = blockIdx.x * 16 + (t >> 3);
    int h = t & 7;
    if (e >= E) return;
    int s = eidx[e];
    int g = eidx[(size_t)E + e];
    const float4* xs = reinterpret_cast<const float4*>(x + (size_t)s * HDIM + h * DHEAD);
    const float4* xt = reinterpret_cast<const float4*>(x + (size_t)g * HDIM + h * DHEAD);
    const float4* hp = reinterpret_cast<const float4*>(he + (size_t)e * HDIM + h * DHEAD);
    const float4* w1 = reinterpret_cast<const float4*>(attw);
    const float4* w2 = reinterpret_cast<const float4*>(attw + DHEAD);
    float acc = attb[0];
#pragma unroll
    for (int i = 0; i < 4; i++) {
        float4 a = xs[i], hh = hp[i], b = xt[i], u = w1[i], v = w2[i];
        acc += (a.x * hh.x) * u.x + (a.y * hh.y) * u.y + (a.z * hh.z) * u.z + (a.w * hh.w) * u.w;
        acc += b.x * v.x + b.y * v.y + b.z * v.z + b.w * v.w;
    }
    float beta = (acc > 0.0f) ? acc : 0.01f * acc;
    g_beta[(size_t)e * NHEAD + h] = beta;
    atomicMax(&g_max[(size_t)g * NHEAD + h], encf(beta));
}

__global__ void attn_exp_kernel(const int* __restrict__ eidx, int E) {
    int i = blockIdx.x * blockDim.x + threadIdx.x;
    if (i >= E * NHEAD) return;
    int e = i >> 3;
    int h = i & 7;
    int g = eidx[(size_t)E + e];
    float m = decf(g_max[(size_t)g * NHEAD + h]);
    float ex = expf(g_beta[i] - m);
    g_beta[i] = ex;
    atomicAdd(&g_den[(size_t)g * NHEAD + h], ex);
}

__global__ void attn_scatter_kernel(const float* __restrict__ x, const int* __restrict__ eidx,
                                    const float* __restrict__ he, int E) {
    int e = blockIdx.x;
    int d = threadIdx.x;
    int s = eidx[e];
    int g = eidx[(size_t)E + e];
    int h = d >> 4;
    float den = g_den[(size_t)g * NHEAD + h];
    float alpha = g_beta[(size_t)e * NHEAD + h] / (den + 1e-16f);
    float v = alpha * x[(size_t)s * HDIM + d] * he[(size_t)e * HDIM + d];
    atomicAdd(&g_agg2[(size_t)g * HDIM + d], v);
}

// ===========================================================================
// Launch
// ===========================================================================
extern "C" void kernel_launch(void* const* d_in, const int* in_sizes, int n_in,
                              void* d_out, int out_size) {
    const float* x     = (const float*)d_in[0];
    const int*   eidx  = (const int*)d_in[1];     // int32 (JAX x64 disabled)
    const float* eattr = (const float*)d_in[2];
    const int*   bidx  = (const int*)d_in[3];
    const float* battr = (const float*)d_in[4];
    const float* Wn2e  = (const float*)d_in[5];
    const float* bn2e  = (const float*)d_in[6];
    const float* A1w   = (const float*)d_in[7];
    const float* A1b   = (const float*)d_in[8];
    const float* A2w   = (const float*)d_in[9];
    const float* A2b   = (const float*)d_in[10];
    const float* A3w   = (const float*)d_in[11];
    const float* A3b   = (const float*)d_in[12];
    const float* Wc1w  = (const float*)d_in[13];
    const float* Wc1b  = (const float*)d_in[14];
    const float* attw  = (const float*)d_in[15];
    const float* attb  = (const float*)d_in[16];
    const float* Wc2w  = (const float*)d_in[17];
    const float* Wc2b  = (const float*)d_in[18];

    const int N  = in_sizes[0] / HDIM;
    const int E  = in_sizes[1] / 2;
    const int E2 = in_sizes[3] / 2;

    float* out    = (float*)d_out;
    float* out_hx = out;
    float* out_he = out + (size_t)N * HDIM;
    float* out_ha = out_he + (size_t)E * HDIM;

    void *p_he0, *p_agg, *p_agg2, *p_den, *p_max, *p_q1, *p_q2, *p_bt, *p_bcomb;
    cudaGetSymbolAddress(&p_he0, g_he0);
    cudaGetSymbolAddress(&p_agg, g_agg);
    cudaGetSymbolAddress(&p_agg2, g_agg2);
    cudaGetSymbolAddress(&p_den, g_den);
    cudaGetSymbolAddress(&p_max, g_max);
    cudaGetSymbolAddress(&p_q1, g_q1);
    cudaGetSymbolAddress(&p_q2, g_q2);
    cudaGetSymbolAddress(&p_bt, g_bt);
    cudaGetSymbolAddress(&p_bcomb, g_bcomb);
    float* bt = (float*)p_bt;

    // Zero accumulators (0x00 is the identity under encf ordering for g_max)
    cudaMemsetAsync(p_agg, 0, (size_t)E * HDIM * sizeof(float), 0);
    cudaMemsetAsync(p_agg2, 0, (size_t)N * HDIM * sizeof(float), 0);
    cudaMemsetAsync(p_den, 0, (size_t)N * NHEAD * sizeof(float), 0);
    cudaMemsetAsync(p_max, 0, (size_t)N * NHEAD * sizeof(unsigned), 0);

    // Pre-convert all weights to tf32 bit patterns
    const int T16K = 128 * 128, T32K = 256 * 128;
    prep_tf32_kernel<<<(T16K + 255) / 256, 256>>>(Wn2e,                 bt + BT_W1, T16K);
    prep_tf32_kernel<<<(T16K + 255) / 256, 256>>>(Wn2e + T16K,          bt + BT_W2, T16K);
    prep_tf32_kernel<<<(T16K + 255) / 256, 256>>>(Wn2e + 2 * T16K,      bt + BT_W3, T16K);
    prep_tf32_kernel<<<(T32K + 255) / 256, 256>>>(Wc1w,                 bt + BT_WC1, T32K);
    prep_tf32_kernel<<<(T16K + 255) / 256, 256>>>(A1w,                  bt + BT_COMB, T16K);
    prep_tf32_kernel<<<(T16K + 255) / 256, 256>>>(A2w,                  bt + BT_COMB + T16K, T16K);
    prep_tf32_kernel<<<(T16K + 255) / 256, 256>>>(A3w,                  bt + BT_COMB + 2 * T16K, T16K);
    prep_tf32_kernel<<<(T32K + 255) / 256, 256>>>(Wc2w,                 bt + BT_WC2, T32K);
    prep_bias_kernel<<<1, 128>>>(A1b, A2b, A3b);

    const int gN  = (N + 127) / 128;
    const int gE  = (E + 127) / 128;
    const int gE2 = (E2 + 127) / 128;

    // Q1 = x @ W1, Q2 = x @ W2
    mma_gemm<4, 128><<<gN, 256>>>(x, nullptr, nullptr, nullptr,
                                  bt + BT_W1, nullptr, (float*)p_q1, N);
    mma_gemm<4, 128><<<gN, 256>>>(x, nullptr, nullptr, nullptr,
                                  bt + BT_W2, nullptr, (float*)p_q2, N);

    // he0 = relu(eattr @ W3 + Q1[src] + Q2[tgt] + b)
    mma_gemm<0, 128><<<gE, 256>>>(eattr, (const float*)p_q1, (const float*)p_q2,
                                  eidx, bt + BT_W3, bn2e, (float*)p_he0, E);

    // agg = segment_sum(he0[bsrc] * battr, btgt)
    scatter_line_kernel<<<E2, HDIM>>>(bidx, battr, E2);

    // he = relu([he0, agg] @ Wc1 + b)
    mma_gemm<1, 256><<<gE, 256>>>((const float*)p_he0, (const float*)p_agg, nullptr,
                                  nullptr, bt + BT_WC1, Wc1b, out_he, E);

    // ha = battr + relu(he0[bsrc]@A1 + he0[btgt]@A2 + battr@A3 + bcomb)
    mma_gemm<2, 384><<<gE2, 256>>>((const float*)p_he0, battr, nullptr, bidx,
                                   bt + BT_COMB, (const float*)p_bcomb, out_ha, E2);

    // Attention
    attn_beta_kernel<<<(E + 15) / 16, 128>>>(x, eidx, out_he, attw, attb, E);
    attn_exp_kernel<<<(E * NHEAD + 255) / 256, 256>>>(eidx, E);
    attn_scatter_kernel<<<E, HDIM>>>(x, eidx, out_he, E);

    // hx = relu([x, agg2] @ Wc2 + b)
    mma_gemm<1, 256><<<gN, 256>>>(x, (const float*)p_agg2, nullptr, nullptr,
                                  bt + BT_WC2, Wc2b, out_hx, N);
}